// round 12
// baseline (speedup 1.0000x reference)
#include <cuda_runtime.h>
#include <cstdint>

// ---------------------------------------------------------------------------
// HopfActivCpx: dz/dt = (a - b*|z|^2) * z, 50 DOPRI5 steps (must match the
// reference's Cartesian DOPRI5 trajectory; cheaper integrators provably fail).
// 4 elements/thread = 2 packed f32x2 groups. Kernel runs at the RF-banking-
// adjusted FFMA2 throughput floor; this round shaves feval 21->20 cycles by
// replacing the NEG1-FMA subtraction with a sign-bit XOR on the idle alu pipe.
// ---------------------------------------------------------------------------

typedef unsigned long long u64;

__device__ __forceinline__ u64 pk(float lo, float hi) {
    u64 r;
    asm("mov.b64 %0, {%1, %2};" : "=l"(r) : "f"(lo), "f"(hi));
    return r;
}
__device__ __forceinline__ float2 up(u64 a) {
    float2 v;
    asm("mov.b64 {%0, %1}, %2;" : "=f"(v.x), "=f"(v.y) : "l"(a));
    return v;
}
__device__ __forceinline__ u64 f2fma(u64 a, u64 b, u64 c) {
    u64 d;
    asm("fma.rn.f32x2 %0, %1, %2, %3;" : "=l"(d) : "l"(a), "l"(b), "l"(c));
    return d;
}
__device__ __forceinline__ u64 f2mul(u64 a, u64 b) {
    u64 d;
    asm("mul.rn.f32x2 %0, %1, %2;" : "=l"(d) : "l"(a), "l"(b));
    return d;
}
// Negate both packed lanes: sign-bit XOR (LOP3x2 on the idle alu pipe).
__device__ __forceinline__ u64 f2neg(u64 a) {
    return a ^ 0x8000000080000000ULL;
}

// Hopf RHS: f(z) = (a - b*|z|^2) * z.  NBr/NBi hold -b.
// 8 fma-pipe ops (20 banking-adjusted cycles) + 1 u64 XOR on alu.
__device__ __forceinline__ void feval(u64 zr, u64 zi,
                                      u64 Ar, u64 Ai, u64 NBr, u64 NBi,
                                      u64& fr, u64& fi) {
    u64 s  = f2fma(zi, zi, f2mul(zr, zr));   // |z|^2
    u64 cr = f2fma(NBr, s, Ar);              // a_re - b_re*s
    u64 ci = f2fma(NBi, s, Ai);              // a_im - b_im*s
    u64 nq = f2neg(f2mul(ci, zi));           // -(ci*zi)  (alu pipe)
    fr = f2fma(cr, zr, nq);                  // cr*zr - ci*zi
    fi = f2fma(ci, zr, f2mul(cr, zi));       // cr*zi + ci*zr
}

__device__ __forceinline__ u64 hcoef(float h, double a) {
    float c = (float)a;      // coefficient rounded to f32 (JAX weak typing)
    float v = h * c;         // fold h in once
    return pk(v, v);
}

__global__ void __launch_bounds__(256, 2)
hopf_dopri5_kernel(const float4* __restrict__ re_z, const float4* __restrict__ im_z,
                   const float4* __restrict__ re_a, const float4* __restrict__ im_a,
                   const float4* __restrict__ re_b, const float4* __restrict__ im_b,
                   const int*    __restrict__ unts,
                   float4* __restrict__ out, int nquads) {
    int i = blockIdx.x * blockDim.x + threadIdx.x;
    if (i >= nquads) return;

    // h = float32((2pi - 2pi/unts) / 50), fp64 like the reference
    const double TWO_PI = 6.283185307179586476925286766559;
    double uu = (double)unts[0];
    float h = (float)((TWO_PI - TWO_PI / uu) / 50.0);

    const u64 HA21 = hcoef(h, 1.0 / 5.0);
    const u64 HA31 = hcoef(h, 3.0 / 40.0);
    const u64 HA32 = hcoef(h, 9.0 / 40.0);
    const u64 HA41 = hcoef(h, 44.0 / 45.0);
    const u64 HA42 = hcoef(h, -56.0 / 15.0);
    const u64 HA43 = hcoef(h, 32.0 / 9.0);
    const u64 HA51 = hcoef(h, 19372.0 / 6561.0);
    const u64 HA52 = hcoef(h, -25360.0 / 2187.0);
    const u64 HA53 = hcoef(h, 64448.0 / 6561.0);
    const u64 HA54 = hcoef(h, -212.0 / 729.0);
    const u64 HA61 = hcoef(h, 9017.0 / 3168.0);
    const u64 HA62 = hcoef(h, -355.0 / 33.0);
    const u64 HA63 = hcoef(h, 46732.0 / 5247.0);
    const u64 HA64 = hcoef(h, 49.0 / 176.0);
    const u64 HA65 = hcoef(h, -5103.0 / 18656.0);
    const u64 HB1  = hcoef(h, 35.0 / 384.0);
    const u64 HB3  = hcoef(h, 500.0 / 1113.0);
    const u64 HB4  = hcoef(h, 125.0 / 192.0);
    const u64 HB5  = hcoef(h, -2187.0 / 6784.0);
    const u64 HB6  = hcoef(h, 11.0 / 84.0);

    float4 vzr = re_z[i], vzi = im_z[i];
    float4 var = re_a[i], vai = im_a[i];
    float4 vbr = re_b[i], vbi = im_b[i];

    u64 Zr[2]  = { pk(vzr.x, vzr.y), pk(vzr.z, vzr.w) };
    u64 Zi[2]  = { pk(vzi.x, vzi.y), pk(vzi.z, vzi.w) };
    u64 Ar[2]  = { pk(var.x, var.y), pk(var.z, var.w) };
    u64 Ai[2]  = { pk(vai.x, vai.y), pk(vai.z, vai.w) };
    u64 NBr[2] = { pk(-vbr.x, -vbr.y), pk(-vbr.z, -vbr.w) };
    u64 NBi[2] = { pk(-vbi.x, -vbi.y), pk(-vbi.z, -vbi.w) };

    #pragma unroll 1
    for (int it = 0; it < 50; ++it) {
        u64 k1r[2], k1i[2], k2r[2], k2i[2], k3r[2], k3i[2];
        u64 k4r[2], k4i[2], k5r[2], k5i[2], k6r[2], k6i[2];
        u64 zr[2], zi[2];

        #pragma unroll
        for (int g = 0; g < 2; ++g)
            feval(Zr[g], Zi[g], Ar[g], Ai[g], NBr[g], NBi[g], k1r[g], k1i[g]);

        #pragma unroll
        for (int g = 0; g < 2; ++g) {
            zr[g] = f2fma(HA21, k1r[g], Zr[g]);
            zi[g] = f2fma(HA21, k1i[g], Zi[g]);
        }
        #pragma unroll
        for (int g = 0; g < 2; ++g)
            feval(zr[g], zi[g], Ar[g], Ai[g], NBr[g], NBi[g], k2r[g], k2i[g]);

        #pragma unroll
        for (int g = 0; g < 2; ++g) {
            zr[g] = f2fma(HA31, k1r[g], Zr[g]); zr[g] = f2fma(HA32, k2r[g], zr[g]);
            zi[g] = f2fma(HA31, k1i[g], Zi[g]); zi[g] = f2fma(HA32, k2i[g], zi[g]);
        }
        #pragma unroll
        for (int g = 0; g < 2; ++g)
            feval(zr[g], zi[g], Ar[g], Ai[g], NBr[g], NBi[g], k3r[g], k3i[g]);

        #pragma unroll
        for (int g = 0; g < 2; ++g) {
            zr[g] = f2fma(HA41, k1r[g], Zr[g]); zr[g] = f2fma(HA42, k2r[g], zr[g]);
            zr[g] = f2fma(HA43, k3r[g], zr[g]);
            zi[g] = f2fma(HA41, k1i[g], Zi[g]); zi[g] = f2fma(HA42, k2i[g], zi[g]);
            zi[g] = f2fma(HA43, k3i[g], zi[g]);
        }
        #pragma unroll
        for (int g = 0; g < 2; ++g)
            feval(zr[g], zi[g], Ar[g], Ai[g], NBr[g], NBi[g], k4r[g], k4i[g]);

        #pragma unroll
        for (int g = 0; g < 2; ++g) {
            zr[g] = f2fma(HA51, k1r[g], Zr[g]); zr[g] = f2fma(HA52, k2r[g], zr[g]);
            zr[g] = f2fma(HA53, k3r[g], zr[g]); zr[g] = f2fma(HA54, k4r[g], zr[g]);
            zi[g] = f2fma(HA51, k1i[g], Zi[g]); zi[g] = f2fma(HA52, k2i[g], zi[g]);
            zi[g] = f2fma(HA53, k3i[g], zi[g]); zi[g] = f2fma(HA54, k4i[g], zi[g]);
        }
        #pragma unroll
        for (int g = 0; g < 2; ++g)
            feval(zr[g], zi[g], Ar[g], Ai[g], NBr[g], NBi[g], k5r[g], k5i[g]);

        // Stage-6 prep (last use of k2), then fold B-weighted k1,k3,k4,k5 into Z
        // BEFORE the k6 feval so k1..k5 die early (register pressure).
        #pragma unroll
        for (int g = 0; g < 2; ++g) {
            zr[g] = f2fma(HA61, k1r[g], Zr[g]); zr[g] = f2fma(HA62, k2r[g], zr[g]);
            zr[g] = f2fma(HA63, k3r[g], zr[g]); zr[g] = f2fma(HA64, k4r[g], zr[g]);
            zr[g] = f2fma(HA65, k5r[g], zr[g]);
            zi[g] = f2fma(HA61, k1i[g], Zi[g]); zi[g] = f2fma(HA62, k2i[g], zi[g]);
            zi[g] = f2fma(HA63, k3i[g], zi[g]); zi[g] = f2fma(HA64, k4i[g], zi[g]);
            zi[g] = f2fma(HA65, k5i[g], zi[g]);

            Zr[g] = f2fma(HB1, k1r[g], Zr[g]); Zr[g] = f2fma(HB3, k3r[g], Zr[g]);
            Zr[g] = f2fma(HB4, k4r[g], Zr[g]); Zr[g] = f2fma(HB5, k5r[g], Zr[g]);
            Zi[g] = f2fma(HB1, k1i[g], Zi[g]); Zi[g] = f2fma(HB3, k3i[g], Zi[g]);
            Zi[g] = f2fma(HB4, k4i[g], Zi[g]); Zi[g] = f2fma(HB5, k5i[g], Zi[g]);
        }
        #pragma unroll
        for (int g = 0; g < 2; ++g)
            feval(zr[g], zi[g], Ar[g], Ai[g], NBr[g], NBi[g], k6r[g], k6i[g]);

        #pragma unroll
        for (int g = 0; g < 2; ++g) {
            Zr[g] = f2fma(HB6, k6r[g], Zr[g]);
            Zi[g] = f2fma(HB6, k6i[g], Zi[g]);
        }
    }

    // Output: stacked [real (N), imag (N)]
    float2 r0 = up(Zr[0]), r1 = up(Zr[1]);
    float2 i0 = up(Zi[0]), i1 = up(Zi[1]);
    out[i]          = make_float4(r0.x, r0.y, r1.x, r1.y);
    out[nquads + i] = make_float4(i0.x, i0.y, i1.x, i1.y);
}

extern "C" void kernel_launch(void* const* d_in, const int* in_sizes, int n_in,
                              void* d_out, int out_size) {
    const float4* re_z = (const float4*)d_in[0];
    const float4* im_z = (const float4*)d_in[1];
    const float4* re_a = (const float4*)d_in[2];
    const float4* im_a = (const float4*)d_in[3];
    const float4* re_b = (const float4*)d_in[4];
    const float4* im_b = (const float4*)d_in[5];
    const int*    unts = (const int*)d_in[7];
    float4* out = (float4*)d_out;

    int n = in_sizes[0];          // 2048*2048 elements
    int nquads = n / 4;           // 4 elements per thread
    int threads = 256;
    int blocks = (nquads + threads - 1) / threads;
    hopf_dopri5_kernel<<<blocks, threads>>>(re_z, im_z, re_a, im_a, re_b, im_b,
                                            unts, out, nquads);
}

// round 13
// speedup vs baseline: 1.0484x; 1.0484x over previous
#include <cuda_runtime.h>
#include <cstdint>

// ---------------------------------------------------------------------------
// HopfActivCpx: dz/dt = (a - b*|z|^2) * z, 50 DOPRI5 steps (must match the
// reference's Cartesian DOPRI5 trajectory; cheaper integrators provably fail).
// 4 elements/thread = 2 packed f32x2 groups, all arithmetic on the fma pipe.
// This round: fr's subtraction via sub.rn.f32x2 (2-operand, rt=2, bit-identical
// to fma(q,-1,p)) instead of the 3-operand NEG1-FMA (rt=3 banking tax), plus
// 2x unroll of the step loop to cut loop-control overhead.
// ---------------------------------------------------------------------------

typedef unsigned long long u64;

__device__ __forceinline__ u64 pk(float lo, float hi) {
    u64 r;
    asm("mov.b64 %0, {%1, %2};" : "=l"(r) : "f"(lo), "f"(hi));
    return r;
}
__device__ __forceinline__ float2 up(u64 a) {
    float2 v;
    asm("mov.b64 {%0, %1}, %2;" : "=f"(v.x), "=f"(v.y) : "l"(a));
    return v;
}
__device__ __forceinline__ u64 f2fma(u64 a, u64 b, u64 c) {
    u64 d;
    asm("fma.rn.f32x2 %0, %1, %2, %3;" : "=l"(d) : "l"(a), "l"(b), "l"(c));
    return d;
}
__device__ __forceinline__ u64 f2mul(u64 a, u64 b) {
    u64 d;
    asm("mul.rn.f32x2 %0, %1, %2;" : "=l"(d) : "l"(a), "l"(b));
    return d;
}
// Packed subtract: rn(p - q), bit-identical to fma(q, -1, p); 2 distinct
// operands -> rt=2 on the fma pipe (vs rt=3 for the 3-operand FMA form).
__device__ __forceinline__ u64 f2sub(u64 p, u64 q) {
    u64 d;
    asm("sub.rn.f32x2 %0, %1, %2;" : "=l"(d) : "l"(p), "l"(q));
    return d;
}

// Hopf RHS: f(z) = (a - b*|z|^2) * z.  NBr/NBi hold -b.
// 9 fma-pipe ops; fr path uses SUB (rt2) instead of NEG1-FMA (rt3).
__device__ __forceinline__ void feval(u64 zr, u64 zi,
                                      u64 Ar, u64 Ai, u64 NBr, u64 NBi,
                                      u64& fr, u64& fi) {
    u64 s  = f2fma(zi, zi, f2mul(zr, zr));   // |z|^2
    u64 cr = f2fma(NBr, s, Ar);              // a_re - b_re*s
    u64 ci = f2fma(NBi, s, Ai);              // a_im - b_im*s
    u64 p  = f2mul(cr, zr);
    u64 q  = f2mul(ci, zi);
    fr = f2sub(p, q);                        // cr*zr - ci*zi
    fi = f2fma(ci, zr, f2mul(cr, zi));       // cr*zi + ci*zr
}

__device__ __forceinline__ u64 hcoef(float h, double a) {
    float c = (float)a;      // coefficient rounded to f32 (JAX weak typing)
    float v = h * c;         // fold h in once
    return pk(v, v);
}

__global__ void __launch_bounds__(256, 2)
hopf_dopri5_kernel(const float4* __restrict__ re_z, const float4* __restrict__ im_z,
                   const float4* __restrict__ re_a, const float4* __restrict__ im_a,
                   const float4* __restrict__ re_b, const float4* __restrict__ im_b,
                   const int*    __restrict__ unts,
                   float4* __restrict__ out, int nquads) {
    int i = blockIdx.x * blockDim.x + threadIdx.x;
    if (i >= nquads) return;

    // h = float32((2pi - 2pi/unts) / 50), fp64 like the reference
    const double TWO_PI = 6.283185307179586476925286766559;
    double uu = (double)unts[0];
    float h = (float)((TWO_PI - TWO_PI / uu) / 50.0);

    const u64 HA21 = hcoef(h, 1.0 / 5.0);
    const u64 HA31 = hcoef(h, 3.0 / 40.0);
    const u64 HA32 = hcoef(h, 9.0 / 40.0);
    const u64 HA41 = hcoef(h, 44.0 / 45.0);
    const u64 HA42 = hcoef(h, -56.0 / 15.0);
    const u64 HA43 = hcoef(h, 32.0 / 9.0);
    const u64 HA51 = hcoef(h, 19372.0 / 6561.0);
    const u64 HA52 = hcoef(h, -25360.0 / 2187.0);
    const u64 HA53 = hcoef(h, 64448.0 / 6561.0);
    const u64 HA54 = hcoef(h, -212.0 / 729.0);
    const u64 HA61 = hcoef(h, 9017.0 / 3168.0);
    const u64 HA62 = hcoef(h, -355.0 / 33.0);
    const u64 HA63 = hcoef(h, 46732.0 / 5247.0);
    const u64 HA64 = hcoef(h, 49.0 / 176.0);
    const u64 HA65 = hcoef(h, -5103.0 / 18656.0);
    const u64 HB1  = hcoef(h, 35.0 / 384.0);
    const u64 HB3  = hcoef(h, 500.0 / 1113.0);
    const u64 HB4  = hcoef(h, 125.0 / 192.0);
    const u64 HB5  = hcoef(h, -2187.0 / 6784.0);
    const u64 HB6  = hcoef(h, 11.0 / 84.0);

    float4 vzr = re_z[i], vzi = im_z[i];
    float4 var = re_a[i], vai = im_a[i];
    float4 vbr = re_b[i], vbi = im_b[i];

    u64 Zr[2]  = { pk(vzr.x, vzr.y), pk(vzr.z, vzr.w) };
    u64 Zi[2]  = { pk(vzi.x, vzi.y), pk(vzi.z, vzi.w) };
    u64 Ar[2]  = { pk(var.x, var.y), pk(var.z, var.w) };
    u64 Ai[2]  = { pk(vai.x, vai.y), pk(vai.z, vai.w) };
    u64 NBr[2] = { pk(-vbr.x, -vbr.y), pk(-vbr.z, -vbr.w) };
    u64 NBi[2] = { pk(-vbi.x, -vbi.y), pk(-vbi.z, -vbi.w) };

    #pragma unroll 2
    for (int it = 0; it < 50; ++it) {
        u64 k1r[2], k1i[2], k2r[2], k2i[2], k3r[2], k3i[2];
        u64 k4r[2], k4i[2], k5r[2], k5i[2], k6r[2], k6i[2];
        u64 zr[2], zi[2];

        #pragma unroll
        for (int g = 0; g < 2; ++g)
            feval(Zr[g], Zi[g], Ar[g], Ai[g], NBr[g], NBi[g], k1r[g], k1i[g]);

        #pragma unroll
        for (int g = 0; g < 2; ++g) {
            zr[g] = f2fma(HA21, k1r[g], Zr[g]);
            zi[g] = f2fma(HA21, k1i[g], Zi[g]);
        }
        #pragma unroll
        for (int g = 0; g < 2; ++g)
            feval(zr[g], zi[g], Ar[g], Ai[g], NBr[g], NBi[g], k2r[g], k2i[g]);

        #pragma unroll
        for (int g = 0; g < 2; ++g) {
            zr[g] = f2fma(HA31, k1r[g], Zr[g]); zr[g] = f2fma(HA32, k2r[g], zr[g]);
            zi[g] = f2fma(HA31, k1i[g], Zi[g]); zi[g] = f2fma(HA32, k2i[g], zi[g]);
        }
        #pragma unroll
        for (int g = 0; g < 2; ++g)
            feval(zr[g], zi[g], Ar[g], Ai[g], NBr[g], NBi[g], k3r[g], k3i[g]);

        #pragma unroll
        for (int g = 0; g < 2; ++g) {
            zr[g] = f2fma(HA41, k1r[g], Zr[g]); zr[g] = f2fma(HA42, k2r[g], zr[g]);
            zr[g] = f2fma(HA43, k3r[g], zr[g]);
            zi[g] = f2fma(HA41, k1i[g], Zi[g]); zi[g] = f2fma(HA42, k2i[g], zi[g]);
            zi[g] = f2fma(HA43, k3i[g], zi[g]);
        }
        #pragma unroll
        for (int g = 0; g < 2; ++g)
            feval(zr[g], zi[g], Ar[g], Ai[g], NBr[g], NBi[g], k4r[g], k4i[g]);

        #pragma unroll
        for (int g = 0; g < 2; ++g) {
            zr[g] = f2fma(HA51, k1r[g], Zr[g]); zr[g] = f2fma(HA52, k2r[g], zr[g]);
            zr[g] = f2fma(HA53, k3r[g], zr[g]); zr[g] = f2fma(HA54, k4r[g], zr[g]);
            zi[g] = f2fma(HA51, k1i[g], Zi[g]); zi[g] = f2fma(HA52, k2i[g], zi[g]);
            zi[g] = f2fma(HA53, k3i[g], zi[g]); zi[g] = f2fma(HA54, k4i[g], zi[g]);
        }
        #pragma unroll
        for (int g = 0; g < 2; ++g)
            feval(zr[g], zi[g], Ar[g], Ai[g], NBr[g], NBi[g], k5r[g], k5i[g]);

        // Stage-6 prep (last use of k2), then fold B-weighted k1,k3,k4,k5 into Z
        // BEFORE the k6 feval so k1..k5 die early (register pressure).
        #pragma unroll
        for (int g = 0; g < 2; ++g) {
            zr[g] = f2fma(HA61, k1r[g], Zr[g]); zr[g] = f2fma(HA62, k2r[g], zr[g]);
            zr[g] = f2fma(HA63, k3r[g], zr[g]); zr[g] = f2fma(HA64, k4r[g], zr[g]);
            zr[g] = f2fma(HA65, k5r[g], zr[g]);
            zi[g] = f2fma(HA61, k1i[g], Zi[g]); zi[g] = f2fma(HA62, k2i[g], zi[g]);
            zi[g] = f2fma(HA63, k3i[g], zi[g]); zi[g] = f2fma(HA64, k4i[g], zi[g]);
            zi[g] = f2fma(HA65, k5i[g], zi[g]);

            Zr[g] = f2fma(HB1, k1r[g], Zr[g]); Zr[g] = f2fma(HB3, k3r[g], Zr[g]);
            Zr[g] = f2fma(HB4, k4r[g], Zr[g]); Zr[g] = f2fma(HB5, k5r[g], Zr[g]);
            Zi[g] = f2fma(HB1, k1i[g], Zi[g]); Zi[g] = f2fma(HB3, k3i[g], Zi[g]);
            Zi[g] = f2fma(HB4, k4i[g], Zi[g]); Zi[g] = f2fma(HB5, k5i[g], Zi[g]);
        }
        #pragma unroll
        for (int g = 0; g < 2; ++g)
            feval(zr[g], zi[g], Ar[g], Ai[g], NBr[g], NBi[g], k6r[g], k6i[g]);

        #pragma unroll
        for (int g = 0; g < 2; ++g) {
            Zr[g] = f2fma(HB6, k6r[g], Zr[g]);
            Zi[g] = f2fma(HB6, k6i[g], Zi[g]);
        }
    }

    // Output: stacked [real (N), imag (N)]
    float2 r0 = up(Zr[0]), r1 = up(Zr[1]);
    float2 i0 = up(Zi[0]), i1 = up(Zi[1]);
    out[i]          = make_float4(r0.x, r0.y, r1.x, r1.y);
    out[nquads + i] = make_float4(i0.x, i0.y, i1.x, i1.y);
}

extern "C" void kernel_launch(void* const* d_in, const int* in_sizes, int n_in,
                              void* d_out, int out_size) {
    const float4* re_z = (const float4*)d_in[0];
    const float4* im_z = (const float4*)d_in[1];
    const float4* re_a = (const float4*)d_in[2];
    const float4* im_a = (const float4*)d_in[3];
    const float4* re_b = (const float4*)d_in[4];
    const float4* im_b = (const float4*)d_in[5];
    const int*    unts = (const int*)d_in[7];
    float4* out = (float4*)d_out;

    int n = in_sizes[0];          // 2048*2048 elements
    int nquads = n / 4;           // 4 elements per thread
    int threads = 256;
    int blocks = (nquads + threads - 1) / threads;
    hopf_dopri5_kernel<<<blocks, threads>>>(re_z, im_z, re_a, im_a, re_b, im_b,
                                            unts, out, nquads);
}

// round 14
// speedup vs baseline: 1.0489x; 1.0005x over previous
#include <cuda_runtime.h>
#include <cstdint>

// ---------------------------------------------------------------------------
// HopfActivCpx: dz/dt = (a - b*|z|^2) * z, 50 DOPRI5 steps (must match the
// reference's Cartesian DOPRI5 trajectory; cheaper integrators provably fail).
// 4 elements/thread = 2 packed f32x2 groups, all arithmetic on the fma pipe.
// This round: fr's subtraction via sub.rn.f32x2 (2-operand, rt=2, bit-identical
// to fma(q,-1,p)) instead of the 3-operand NEG1-FMA (rt=3 banking tax), plus
// 2x unroll of the step loop to cut loop-control overhead.
// ---------------------------------------------------------------------------

typedef unsigned long long u64;

__device__ __forceinline__ u64 pk(float lo, float hi) {
    u64 r;
    asm("mov.b64 %0, {%1, %2};" : "=l"(r) : "f"(lo), "f"(hi));
    return r;
}
__device__ __forceinline__ float2 up(u64 a) {
    float2 v;
    asm("mov.b64 {%0, %1}, %2;" : "=f"(v.x), "=f"(v.y) : "l"(a));
    return v;
}
__device__ __forceinline__ u64 f2fma(u64 a, u64 b, u64 c) {
    u64 d;
    asm("fma.rn.f32x2 %0, %1, %2, %3;" : "=l"(d) : "l"(a), "l"(b), "l"(c));
    return d;
}
__device__ __forceinline__ u64 f2mul(u64 a, u64 b) {
    u64 d;
    asm("mul.rn.f32x2 %0, %1, %2;" : "=l"(d) : "l"(a), "l"(b));
    return d;
}
// Packed subtract: rn(p - q), bit-identical to fma(q, -1, p); 2 distinct
// operands -> rt=2 on the fma pipe (vs rt=3 for the 3-operand FMA form).
__device__ __forceinline__ u64 f2sub(u64 p, u64 q) {
    u64 d;
    asm("sub.rn.f32x2 %0, %1, %2;" : "=l"(d) : "l"(p), "l"(q));
    return d;
}

// Hopf RHS: f(z) = (a - b*|z|^2) * z.  NBr/NBi hold -b.
// 9 fma-pipe ops; fr path uses SUB (rt2) instead of NEG1-FMA (rt3).
__device__ __forceinline__ void feval(u64 zr, u64 zi,
                                      u64 Ar, u64 Ai, u64 NBr, u64 NBi,
                                      u64& fr, u64& fi) {
    u64 s  = f2fma(zi, zi, f2mul(zr, zr));   // |z|^2
    u64 cr = f2fma(NBr, s, Ar);              // a_re - b_re*s
    u64 ci = f2fma(NBi, s, Ai);              // a_im - b_im*s
    u64 p  = f2mul(cr, zr);
    u64 q  = f2mul(ci, zi);
    fr = f2sub(p, q);                        // cr*zr - ci*zi
    fi = f2fma(ci, zr, f2mul(cr, zi));       // cr*zi + ci*zr
}

__device__ __forceinline__ u64 hcoef(float h, double a) {
    float c = (float)a;      // coefficient rounded to f32 (JAX weak typing)
    float v = h * c;         // fold h in once
    return pk(v, v);
}

__global__ void __launch_bounds__(256, 2)
hopf_dopri5_kernel(const float4* __restrict__ re_z, const float4* __restrict__ im_z,
                   const float4* __restrict__ re_a, const float4* __restrict__ im_a,
                   const float4* __restrict__ re_b, const float4* __restrict__ im_b,
                   const int*    __restrict__ unts,
                   float4* __restrict__ out, int nquads) {
    int i = blockIdx.x * blockDim.x + threadIdx.x;
    if (i >= nquads) return;

    // h = float32((2pi - 2pi/unts) / 50), fp64 like the reference
    const double TWO_PI = 6.283185307179586476925286766559;
    double uu = (double)unts[0];
    float h = (float)((TWO_PI - TWO_PI / uu) / 50.0);

    const u64 HA21 = hcoef(h, 1.0 / 5.0);
    const u64 HA31 = hcoef(h, 3.0 / 40.0);
    const u64 HA32 = hcoef(h, 9.0 / 40.0);
    const u64 HA41 = hcoef(h, 44.0 / 45.0);
    const u64 HA42 = hcoef(h, -56.0 / 15.0);
    const u64 HA43 = hcoef(h, 32.0 / 9.0);
    const u64 HA51 = hcoef(h, 19372.0 / 6561.0);
    const u64 HA52 = hcoef(h, -25360.0 / 2187.0);
    const u64 HA53 = hcoef(h, 64448.0 / 6561.0);
    const u64 HA54 = hcoef(h, -212.0 / 729.0);
    const u64 HA61 = hcoef(h, 9017.0 / 3168.0);
    const u64 HA62 = hcoef(h, -355.0 / 33.0);
    const u64 HA63 = hcoef(h, 46732.0 / 5247.0);
    const u64 HA64 = hcoef(h, 49.0 / 176.0);
    const u64 HA65 = hcoef(h, -5103.0 / 18656.0);
    const u64 HB1  = hcoef(h, 35.0 / 384.0);
    const u64 HB3  = hcoef(h, 500.0 / 1113.0);
    const u64 HB4  = hcoef(h, 125.0 / 192.0);
    const u64 HB5  = hcoef(h, -2187.0 / 6784.0);
    const u64 HB6  = hcoef(h, 11.0 / 84.0);

    float4 vzr = re_z[i], vzi = im_z[i];
    float4 var = re_a[i], vai = im_a[i];
    float4 vbr = re_b[i], vbi = im_b[i];

    u64 Zr[2]  = { pk(vzr.x, vzr.y), pk(vzr.z, vzr.w) };
    u64 Zi[2]  = { pk(vzi.x, vzi.y), pk(vzi.z, vzi.w) };
    u64 Ar[2]  = { pk(var.x, var.y), pk(var.z, var.w) };
    u64 Ai[2]  = { pk(vai.x, vai.y), pk(vai.z, vai.w) };
    u64 NBr[2] = { pk(-vbr.x, -vbr.y), pk(-vbr.z, -vbr.w) };
    u64 NBi[2] = { pk(-vbi.x, -vbi.y), pk(-vbi.z, -vbi.w) };

    #pragma unroll 2
    for (int it = 0; it < 50; ++it) {
        u64 k1r[2], k1i[2], k2r[2], k2i[2], k3r[2], k3i[2];
        u64 k4r[2], k4i[2], k5r[2], k5i[2], k6r[2], k6i[2];
        u64 zr[2], zi[2];

        #pragma unroll
        for (int g = 0; g < 2; ++g)
            feval(Zr[g], Zi[g], Ar[g], Ai[g], NBr[g], NBi[g], k1r[g], k1i[g]);

        #pragma unroll
        for (int g = 0; g < 2; ++g) {
            zr[g] = f2fma(HA21, k1r[g], Zr[g]);
            zi[g] = f2fma(HA21, k1i[g], Zi[g]);
        }
        #pragma unroll
        for (int g = 0; g < 2; ++g)
            feval(zr[g], zi[g], Ar[g], Ai[g], NBr[g], NBi[g], k2r[g], k2i[g]);

        #pragma unroll
        for (int g = 0; g < 2; ++g) {
            zr[g] = f2fma(HA31, k1r[g], Zr[g]); zr[g] = f2fma(HA32, k2r[g], zr[g]);
            zi[g] = f2fma(HA31, k1i[g], Zi[g]); zi[g] = f2fma(HA32, k2i[g], zi[g]);
        }
        #pragma unroll
        for (int g = 0; g < 2; ++g)
            feval(zr[g], zi[g], Ar[g], Ai[g], NBr[g], NBi[g], k3r[g], k3i[g]);

        #pragma unroll
        for (int g = 0; g < 2; ++g) {
            zr[g] = f2fma(HA41, k1r[g], Zr[g]); zr[g] = f2fma(HA42, k2r[g], zr[g]);
            zr[g] = f2fma(HA43, k3r[g], zr[g]);
            zi[g] = f2fma(HA41, k1i[g], Zi[g]); zi[g] = f2fma(HA42, k2i[g], zi[g]);
            zi[g] = f2fma(HA43, k3i[g], zi[g]);
        }
        #pragma unroll
        for (int g = 0; g < 2; ++g)
            feval(zr[g], zi[g], Ar[g], Ai[g], NBr[g], NBi[g], k4r[g], k4i[g]);

        #pragma unroll
        for (int g = 0; g < 2; ++g) {
            zr[g] = f2fma(HA51, k1r[g], Zr[g]); zr[g] = f2fma(HA52, k2r[g], zr[g]);
            zr[g] = f2fma(HA53, k3r[g], zr[g]); zr[g] = f2fma(HA54, k4r[g], zr[g]);
            zi[g] = f2fma(HA51, k1i[g], Zi[g]); zi[g] = f2fma(HA52, k2i[g], zi[g]);
            zi[g] = f2fma(HA53, k3i[g], zi[g]); zi[g] = f2fma(HA54, k4i[g], zi[g]);
        }
        #pragma unroll
        for (int g = 0; g < 2; ++g)
            feval(zr[g], zi[g], Ar[g], Ai[g], NBr[g], NBi[g], k5r[g], k5i[g]);

        // Stage-6 prep (last use of k2), then fold B-weighted k1,k3,k4,k5 into Z
        // BEFORE the k6 feval so k1..k5 die early (register pressure).
        #pragma unroll
        for (int g = 0; g < 2; ++g) {
            zr[g] = f2fma(HA61, k1r[g], Zr[g]); zr[g] = f2fma(HA62, k2r[g], zr[g]);
            zr[g] = f2fma(HA63, k3r[g], zr[g]); zr[g] = f2fma(HA64, k4r[g], zr[g]);
            zr[g] = f2fma(HA65, k5r[g], zr[g]);
            zi[g] = f2fma(HA61, k1i[g], Zi[g]); zi[g] = f2fma(HA62, k2i[g], zi[g]);
            zi[g] = f2fma(HA63, k3i[g], zi[g]); zi[g] = f2fma(HA64, k4i[g], zi[g]);
            zi[g] = f2fma(HA65, k5i[g], zi[g]);

            Zr[g] = f2fma(HB1, k1r[g], Zr[g]); Zr[g] = f2fma(HB3, k3r[g], Zr[g]);
            Zr[g] = f2fma(HB4, k4r[g], Zr[g]); Zr[g] = f2fma(HB5, k5r[g], Zr[g]);
            Zi[g] = f2fma(HB1, k1i[g], Zi[g]); Zi[g] = f2fma(HB3, k3i[g], Zi[g]);
            Zi[g] = f2fma(HB4, k4i[g], Zi[g]); Zi[g] = f2fma(HB5, k5i[g], Zi[g]);
        }
        #pragma unroll
        for (int g = 0; g < 2; ++g)
            feval(zr[g], zi[g], Ar[g], Ai[g], NBr[g], NBi[g], k6r[g], k6i[g]);

        #pragma unroll
        for (int g = 0; g < 2; ++g) {
            Zr[g] = f2fma(HB6, k6r[g], Zr[g]);
            Zi[g] = f2fma(HB6, k6i[g], Zi[g]);
        }
    }

    // Output: stacked [real (N), imag (N)]
    float2 r0 = up(Zr[0]), r1 = up(Zr[1]);
    float2 i0 = up(Zi[0]), i1 = up(Zi[1]);
    out[i]          = make_float4(r0.x, r0.y, r1.x, r1.y);
    out[nquads + i] = make_float4(i0.x, i0.y, i1.x, i1.y);
}

extern "C" void kernel_launch(void* const* d_in, const int* in_sizes, int n_in,
                              void* d_out, int out_size) {
    const float4* re_z = (const float4*)d_in[0];
    const float4* im_z = (const float4*)d_in[1];
    const float4* re_a = (const float4*)d_in[2];
    const float4* im_a = (const float4*)d_in[3];
    const float4* re_b = (const float4*)d_in[4];
    const float4* im_b = (const float4*)d_in[5];
    const int*    unts = (const int*)d_in[7];
    float4* out = (float4*)d_out;

    int n = in_sizes[0];          // 2048*2048 elements
    int nquads = n / 4;           // 4 elements per thread
    int threads = 256;
    int blocks = (nquads + threads - 1) / threads;
    hopf_dopri5_kernel<<<blocks, threads>>>(re_z, im_z, re_a, im_a, re_b, im_b,
                                            unts, out, nquads);
}